// round 4
// baseline (speedup 1.0000x reference)
#include <cuda_runtime.h>
#include <cuda_bf16.h>

// Problem constants
#define BB 4
#define MM 2048
#define HH 16
#define NJ 16            // Taylor terms j = 0..15
#define SCALE 0.3535533905932738f   // (128//16)^-0.5 = 8^-0.5

// 1/j! for j=0..15
__constant__ float c_F[NJ] = {
    1.0f,
    1.0f,
    5.0e-1f,
    1.6666666666666666e-1f,
    4.1666666666666664e-2f,
    8.3333333333333332e-3f,
    1.3888888888888889e-3f,
    1.9841269841269841e-4f,
    2.4801587301587302e-5f,
    2.7557319223985893e-6f,
    2.7557319223985894e-7f,
    2.5052108385441720e-8f,
    2.0876756987868100e-9f,
    1.6059043836821616e-10f,
    1.1470745597729726e-11f,
    7.6471637318198174e-13f
};

// Globals (no allocation allowed)
__device__ float g_SA[NJ * 16];   // [j][t] : sum_s A(s,t)^j
__device__ float g_AG[NJ * 16];   // [j][t] : sum_s A(s,t)^j * G(t,s)
__device__ float g_y[BB * MM];    // residual + attention output (pre-LN)

// ---------------------------------------------------------------------------
// Kernel 1: build A(s,t), G(t,s), then SA_j(t), AG_j(t).  1 block, 256 thr.
// ---------------------------------------------------------------------------
__global__ void k_setup(const float* __restrict__ wq, const float* __restrict__ wk,
                        const float* __restrict__ wv, const float* __restrict__ wf) {
    __shared__ float Ash[256];   // [s*16+t]
    __shared__ float Gsh[256];   // [t*16+s]
    int tid = threadIdx.x;
    int s = tid >> 4, t = tid & 15;
    const float* pq = wq + s * 128;
    const float* pk = wk + t * 128;
    const float* pv = wv + t * 128;
    const float* pf = wf + s * 128;
    float c = 0.f, g = 0.f;
#pragma unroll 8
    for (int d = 0; d < 128; d++) {
        c = fmaf(pq[d], pk[d], c);
        g = fmaf(pv[d], pf[d], g);
    }
    Ash[s * 16 + t] = SCALE * c;   // A(s,t)
    Gsh[t * 16 + s] = g;           // G(t,s)
    __syncthreads();

    if (tid < 16) {
        int tt = tid;
        float pw[16];
#pragma unroll
        for (int ss = 0; ss < 16; ss++) pw[ss] = 1.f;
        for (int j = 0; j < NJ; j++) {
            float sa = 0.f, ag = 0.f;
#pragma unroll
            for (int ss = 0; ss < 16; ss++) {
                sa += pw[ss];
                ag = fmaf(pw[ss], Gsh[tt * 16 + ss], ag);
                pw[ss] *= Ash[ss * 16 + tt];
            }
            g_SA[j * 16 + tt] = sa;
            g_AG[j * 16 + tt] = ag;
        }
    }
}

// ---------------------------------------------------------------------------
// Kernel 2: per (b,h) unit. 64 blocks x 256 threads.
// ---------------------------------------------------------------------------
__global__ void k_attn(const float* __restrict__ query,
                       const float* __restrict__ key,
                       const float* __restrict__ value) {
    const int b = blockIdx.x >> 4;
    const int h = blockIdx.x & 15;
    const int tid = threadIdx.x;

    __shared__ float Qs[128], Ks[128], Vs[128];
    __shared__ float QMp[4][NJ];        // per-warp partial moments of Q
    __shared__ float cz[NJ][16];        // Z-polynomial coefficients per t
    __shared__ float Kpow[NJ][128];     // K_p^j
    __shared__ float iv[128][17];       // V_p / Z(p,t)   (padded stride 17)
    __shared__ float U[NJ][16];
    __shared__ float Wf[NJ];

    const float* qb = query + b * MM + h * 128;
    const float* kb = key   + b * MM + h * 128;
    const float* vb = value + b * MM + h * 128;

    if (tid < 128) {
        float q = qb[tid];
        float k = kb[tid];
        Qs[tid] = q; Ks[tid] = k; Vs[tid] = vb[tid];
        float qp = 1.f, kp = 1.f;
        int lane = tid & 31, w = tid >> 5;
#pragma unroll
        for (int j = 0; j < NJ; j++) {
            Kpow[j][tid] = kp;
            kp *= k;
            float v = qp;
#pragma unroll
            for (int o = 16; o; o >>= 1) v += __shfl_down_sync(0xffffffffu, v, o);
            if (lane == 0) QMp[w][j] = v;
            qp *= q;
        }
    }
    __syncthreads();

    // cz[j][t] = F_j * QM_j * SA_j(t)   (NJ*16 = 256 threads, one each)
    {
        int j = tid >> 4, t = tid & 15;
        float qm = QMp[0][j] + QMp[1][j] + QMp[2][j] + QMp[3][j];
        cz[j][t] = c_F[j] * qm * g_SA[j * 16 + t];
    }
    __syncthreads();

    // Z(p,t) via Horner in K_p; iv = V_p / Z
    if (tid < 128) {
        float k = Ks[tid], v = Vs[tid];
#pragma unroll
        for (int t = 0; t < 16; t++) {
            float z = cz[NJ - 1][t];
#pragma unroll
            for (int j = NJ - 2; j >= 0; j--) z = fmaf(z, k, cz[j][t]);
            iv[tid][t] = __fdividef(v, z);
        }
    }
    __syncthreads();

    // U[j][t] = sum_p Kpow[j][p] * iv[p][t]   (256 threads, one (j,t) each)
    {
        int j = tid >> 4, t = tid & 15;
        float u = 0.f;
#pragma unroll 8
        for (int p = 0; p < 128; p++) u = fmaf(Kpow[j][p], iv[p][t], u);
        U[j][t] = u;
    }
    __syncthreads();

    // Wf[j] = F_j * sum_t AG_j(t) * U_j(t)
    if (tid < NJ) {
        float wsum = 0.f;
#pragma unroll
        for (int t = 0; t < 16; t++) wsum = fmaf(g_AG[tid * 16 + t], U[tid][t], wsum);
        Wf[tid] = c_F[tid] * wsum;
    }
    __syncthreads();

    // out[b, 128h + r] = Q_r + sum_j Wf[j] Q_r^j  (Horner)
    if (tid < 128) {
        float q = Qs[tid];
        float val = Wf[NJ - 1];
#pragma unroll
        for (int j = NJ - 2; j >= 0; j--) val = fmaf(val, q, Wf[j]);
        g_y[b * MM + h * 128 + tid] = q + val;
    }
}

// ---------------------------------------------------------------------------
// Kernel 3: LayerNorm over M per batch. 4 blocks x 256 threads.
// ---------------------------------------------------------------------------
__global__ void k_ln(const float* __restrict__ ln_w, const float* __restrict__ ln_b,
                     float* __restrict__ out) {
    const int b = blockIdx.x;
    const int tid = threadIdx.x;
    const float* y = g_y + b * MM;

    float loc[8];
    float s = 0.f, s2 = 0.f;
#pragma unroll
    for (int i = 0; i < 8; i++) {
        float v = y[tid + i * 256];
        loc[i] = v;
        s += v;
        s2 = fmaf(v, v, s2);
    }
    __shared__ float red0[8], red1[8];
    __shared__ float mu_s, rs_s;
    int lane = tid & 31, w = tid >> 5;
#pragma unroll
    for (int o = 16; o; o >>= 1) {
        s  += __shfl_down_sync(0xffffffffu, s,  o);
        s2 += __shfl_down_sync(0xffffffffu, s2, o);
    }
    if (lane == 0) { red0[w] = s; red1[w] = s2; }
    __syncthreads();
    if (tid == 0) {
        float S = 0.f, S2 = 0.f;
#pragma unroll
        for (int i = 0; i < 8; i++) { S += red0[i]; S2 += red1[i]; }
        float mu  = S * (1.0f / MM);
        float var = S2 * (1.0f / MM) - mu * mu;
        mu_s = mu;
        rs_s = rsqrtf(var + 1e-5f);
    }
    __syncthreads();
    float mu = mu_s, rs = rs_s;
#pragma unroll
    for (int i = 0; i < 8; i++) {
        int m = tid + i * 256;
        out[b * MM + m] = (loc[i] - mu) * rs * ln_w[m] + ln_b[m];
    }
}

// ---------------------------------------------------------------------------
extern "C" void kernel_launch(void* const* d_in, const int* in_sizes, int n_in,
                              void* d_out, int out_size) {
    const float* query = (const float*)d_in[0];
    const float* key_  = (const float*)d_in[1];
    const float* value = (const float*)d_in[2];
    const float* wq    = (const float*)d_in[3];
    const float* wk    = (const float*)d_in[4];
    const float* wv    = (const float*)d_in[5];
    const float* wf    = (const float*)d_in[6];
    const float* lw    = (const float*)d_in[7];
    const float* lb    = (const float*)d_in[8];
    float* out = (float*)d_out;

    k_setup<<<1, 256>>>(wq, wk, wv, wf);
    k_attn<<<BB * HH, 256>>>(query, key_, value);
    k_ln<<<BB, 256>>>(lw, lb, out);
}

// round 5
// speedup vs baseline: 2.4637x; 2.4637x over previous
#include <cuda_runtime.h>
#include <cuda_bf16.h>

#define BB 4
#define MM 2048
#define HH 16
#define NJ 16
#define SCALE 0.3535533905932738f   // (128//16)^-0.5

__constant__ float c_F[NJ] = {
    1.0f, 1.0f, 5.0e-1f, 1.6666666666666666e-1f,
    4.1666666666666664e-2f, 8.3333333333333332e-3f,
    1.3888888888888889e-3f, 1.9841269841269841e-4f,
    2.4801587301587302e-5f, 2.7557319223985893e-6f,
    2.7557319223985894e-7f, 2.5052108385441720e-8f,
    2.0876756987868100e-9f, 1.6059043836821616e-10f,
    1.1470745597729726e-11f, 7.6471637318198174e-13f
};

__device__ float g_y[BB * MM];   // residual + attention output (pre-LN)
__device__ int   g_cnt[BB];      // zero-initialized; reset at end of each run

__global__ void __launch_bounds__(256, 1)
k_fused(const float* __restrict__ query, const float* __restrict__ key_,
        const float* __restrict__ value, const float* __restrict__ wq,
        const float* __restrict__ wk,    const float* __restrict__ wv,
        const float* __restrict__ wf,    const float* __restrict__ lnw,
        const float* __restrict__ lnb,   float* __restrict__ out) {
    const int b   = blockIdx.x >> 4;
    const int h   = blockIdx.x & 15;
    const int tid = threadIdx.x;

    // Overlay region: phase1 = weight staging (8448 f), phase2 = Kpow+iv (4224 f)
    __shared__ float buf[8448];
    __shared__ float Ash[256];          // A(s,t) at [s*16+t]
    __shared__ float Gsh[256];          // G(t,s) at [t*16+s]
    __shared__ float SA[NJ * 16];       // sum_s A(s,t)^j
    __shared__ float AG[NJ * 16];       // sum_s A(s,t)^j G(t,s)
    __shared__ float Qs[128], Ks[128], Vs[128];
    __shared__ float QMp[4][NJ];
    __shared__ float cz[NJ][16];
    __shared__ float U[NJ][16];
    __shared__ float Wf[NJ];
    __shared__ float red0[8], red1[8], mu_s, rs_s;
    __shared__ int   isLast;

    float* Qw = buf;            // [s*128+d]  (2048)
    float* Fw = buf + 2048;     // [s*128+d]  (2048)
    float* Kt = buf + 4096;     // [d*17+t]   (2176, pad-17 conflict-free)
    float* Vt = buf + 6272;     // [d*17+t]   (2176)

    // ---- Phase 1: stage weights (coalesced) + per-head q/k/v ----
#pragma unroll
    for (int i = tid; i < 2048; i += 256) {
        Qw[i] = wq[i];
        Fw[i] = wf[i];
        int d = i & 127, t = i >> 7;
        Kt[d * 17 + t] = wk[i];
        Vt[d * 17 + t] = wv[i];
    }
    if (tid < 128) {
        Qs[tid] = query[b * MM + h * 128 + tid];
        Ks[tid] = key_ [b * MM + h * 128 + tid];
        Vs[tid] = value[b * MM + h * 128 + tid];
    }
    __syncthreads();

    // ---- A(s,t) = SCALE * <wq_s, wk_t>,  G(t,s) = <wv_t, wf_s>  (256 dots) ----
    {
        int s = tid >> 4, t = tid & 15;
        const float* pq = Qw + s * 128;
        const float* pf = Fw + s * 128;
        float a = 0.f, g = 0.f;
#pragma unroll 8
        for (int d = 0; d < 128; d++) {
            float kt = Kt[d * 17 + t];
            float vt = Vt[d * 17 + t];
            a = fmaf(pq[d], kt, a);
            g = fmaf(vt, pf[d], g);
        }
        Ash[s * 16 + t] = SCALE * a;
        Gsh[t * 16 + s] = g;
    }
    __syncthreads();        // staging region now dead -> reuse buf

    float* Kpow = buf;              // [j*128 + p]   (2048)
    float* iv   = buf + NJ * 128;   // [p*17 + t]    (2176)

    // ---- Phase 2 (parallel branches):
    //   warps 0-3 (tid<128): K powers + Q moments
    //   warp 4 lanes 0-15  : SA_j(t), AG_j(t) power series
    if (tid < 128) {
        float q = Qs[tid], k = Ks[tid];
        float qp = 1.f, kp = 1.f;
        int lane = tid & 31, w = tid >> 5;
#pragma unroll
        for (int j = 0; j < NJ; j++) {
            Kpow[j * 128 + tid] = kp;
            kp *= k;
            float v = qp;
#pragma unroll
            for (int o = 16; o; o >>= 1) v += __shfl_down_sync(0xffffffffu, v, o);
            if (lane == 0) QMp[w][j] = v;
            qp *= q;
        }
    } else if (tid < 144) {
        int tt = tid - 128;
        float pw[16];
#pragma unroll
        for (int ss = 0; ss < 16; ss++) pw[ss] = 1.f;
        for (int j = 0; j < NJ; j++) {
            float sa = 0.f, ag = 0.f;
#pragma unroll
            for (int ss = 0; ss < 16; ss++) {
                sa += pw[ss];
                ag = fmaf(pw[ss], Gsh[tt * 16 + ss], ag);
                pw[ss] *= Ash[ss * 16 + tt];
            }
            SA[j * 16 + tt] = sa;
            AG[j * 16 + tt] = ag;
        }
    }
    __syncthreads();

    // ---- cz[j][t] = F_j * QM_j * SA_j(t) ----
    {
        int j = tid >> 4, t = tid & 15;
        float qm = QMp[0][j] + QMp[1][j] + QMp[2][j] + QMp[3][j];
        cz[j][t] = c_F[j] * qm * SA[j * 16 + t];
    }
    __syncthreads();

    // ---- Z(p,t) by Horner in K_p;  iv = V_p / Z ----
    if (tid < 128) {
        float k = Ks[tid], v = Vs[tid];
#pragma unroll
        for (int t = 0; t < 16; t++) {
            float z = cz[NJ - 1][t];
#pragma unroll
            for (int j = NJ - 2; j >= 0; j--) z = fmaf(z, k, cz[j][t]);
            iv[tid * 17 + t] = __fdividef(v, z);
        }
    }
    __syncthreads();

    // ---- U[j][t] = sum_p K_p^j * iv[p][t] ----
    {
        int j = tid >> 4, t = tid & 15;
        float u = 0.f;
#pragma unroll 8
        for (int p = 0; p < 128; p++)
            u = fmaf(Kpow[j * 128 + p], iv[p * 17 + t], u);
        U[j][t] = u;
    }
    __syncthreads();

    // ---- Wf[j] = F_j * sum_t AG_j(t) * U_j(t) ----
    if (tid < NJ) {
        float wsum = 0.f;
#pragma unroll
        for (int t = 0; t < 16; t++) wsum = fmaf(AG[tid * 16 + t], U[tid][t], wsum);
        Wf[tid] = c_F[tid] * wsum;
    }
    __syncthreads();

    // ---- y[b, 128h+r] = Q_r + sum_j Wf[j] Q_r^j  (Horner) ----
    if (tid < 128) {
        float q = Qs[tid];
        float val = Wf[NJ - 1];
#pragma unroll
        for (int j = NJ - 2; j >= 0; j--) val = fmaf(val, q, Wf[j]);
        g_y[b * MM + h * 128 + tid] = q + val;
    }

    // ---- Last block of each batch performs LayerNorm (threadFenceReduction) ----
    __threadfence();
    __syncthreads();
    if (tid == 0) {
        int old = atomicAdd(&g_cnt[b], 1);
        isLast = (old == HH - 1);
    }
    __syncthreads();
    if (!isLast) return;
    __threadfence();   // acquire: make all blocks' g_y writes visible

    const float* y = g_y + b * MM;
    float loc[8];
    float s = 0.f, s2 = 0.f;
#pragma unroll
    for (int i = 0; i < 8; i++) {
        float v = y[tid + i * 256];
        loc[i] = v;
        s += v;
        s2 = fmaf(v, v, s2);
    }
    int lane = tid & 31, w = tid >> 5;
#pragma unroll
    for (int o = 16; o; o >>= 1) {
        s  += __shfl_down_sync(0xffffffffu, s,  o);
        s2 += __shfl_down_sync(0xffffffffu, s2, o);
    }
    if (lane == 0) { red0[w] = s; red1[w] = s2; }
    __syncthreads();
    if (tid == 0) {
        float S = 0.f, S2 = 0.f;
#pragma unroll
        for (int i = 0; i < 8; i++) { S += red0[i]; S2 += red1[i]; }
        float mu  = S * (1.0f / MM);
        float var = S2 * (1.0f / MM) - mu * mu;
        mu_s = mu;
        rs_s = rsqrtf(var + 1e-5f);
        g_cnt[b] = 0;   // reset for next graph replay
    }
    __syncthreads();
    float mu = mu_s, rs = rs_s;
#pragma unroll
    for (int i = 0; i < 8; i++) {
        int m = tid + i * 256;
        out[b * MM + m] = (loc[i] - mu) * rs * lnw[m] + lnb[m];
    }
}

extern "C" void kernel_launch(void* const* d_in, const int* in_sizes, int n_in,
                              void* d_out, int out_size) {
    const float* query = (const float*)d_in[0];
    const float* key_  = (const float*)d_in[1];
    const float* value = (const float*)d_in[2];
    const float* wq    = (const float*)d_in[3];
    const float* wk    = (const float*)d_in[4];
    const float* wv    = (const float*)d_in[5];
    const float* wf    = (const float*)d_in[6];
    const float* lw    = (const float*)d_in[7];
    const float* lb    = (const float*)d_in[8];
    float* out = (float*)d_out;

    k_fused<<<BB * HH, 256>>>(query, key_, value, wq, wk, wv, wf, lw, lb, out);
}